// round 11
// baseline (speedup 1.0000x reference)
#include <cuda_runtime.h>
#include <math.h>

#ifndef M_PI
#define M_PI 3.14159265358979323846
#endif

#define NA   1152
#define ND   736
#define NP   512
#define PADN 2048
#define HALF (PADN/2 + 1)
#define ESZ  1472      // extended filter: s_e[i] = h[(i-736) mod 2048], i in [0,1472)

// ---- device scratch (static allocations only) ----
__device__ float  g_filt[HALF];        // rfft half-spectrum filter
__device__ float  g_h[PADN];           // spatial filter (A*D^2 and pi/2NA folded in)
__device__ float4 g_ang[NA];           // (cos, sin, K*cos, K*sin) per angle
__device__ float2 g_flt2[NA * ND];     // filtered sinogram as (v[i], v[i+1]) pairs

// ---------------------------------------------------------------------------
__device__ __forceinline__ double block_reduce128(double v) {
    __shared__ double s[4];
    int lane = threadIdx.x & 31, w = threadIdx.x >> 5;
    #pragma unroll
    for (int o = 16; o > 0; o >>= 1)
        v += __shfl_down_sync(0xffffffffu, v, o);
    if (lane == 0) s[w] = v;
    __syncthreads();
    double t = 0.0;
    if (threadIdx.x == 0) {
        #pragma unroll
        for (int i = 0; i < 4; i++) t += s[i];
    }
    return t;
}

// ---------------------------------------------------------------------------
// FILT[k] = 2*(0.25 + 2*sum_{odd n<=1023} (-1/(pi n)^2) cos(2 pi k n / 2048))
//           * (k==0 ? 1 : sin(pi k/2048)/(pi k/2048))
__global__ void k_filt_coeff() {
    int k = blockIdx.x;  // 0..1024
    double p = 0.0;
    for (int n = 2 * threadIdx.x + 1; n < 1024; n += 256) {
        int m = (k * n) & (PADN - 1);                 // exact reduction mod 2048
        float c = cospif((float)m * (1.0f / 1024.0f));
        p += (double)(c / ((float)n * (float)n));
    }
    double s = block_reduce128(p);
    if (threadIdx.x == 0) {
        const double inv_pi2 = 1.0 / (M_PI * M_PI);
        double F = 2.0 * (0.25 - 2.0 * inv_pi2 * s);
        if (k > 0) {
            double x = M_PI * (double)k / (double)PADN;
            F *= sin(x) / x;
        }
        g_filt[k] = (float)F;
    }
}

// h[n] = irdft(FILT)[n], scaled by pi/(2*NA) * A * D^2  (A = HU rescale slope)
__global__ void k_spatial() {
    int n = blockIdx.x;  // 0..2047
    double p = 0.0;
    for (int k = threadIdx.x + 1; k < PADN / 2; k += 128) {
        int m = (k * n) & (PADN - 1);
        float c = cospif((float)m * (1.0f / 1024.0f));
        p += (double)(g_filt[k] * c);
    }
    double s = block_reduce128(p);
    if (threadIdx.x == 0) {
        double v = (double)g_filt[0] + 2.0 * s
                 + (double)g_filt[PADN / 2] * ((n & 1) ? -1.0 : 1.0);
        const double Dd = (1.0 / 0.7) * 595.0;
        const double A  = 1000.0 / (0.0192 * 4096.0);
        v *= (1.0 / (double)PADN) * (M_PI / (2.0 * (double)NA)) * A * Dd * Dd;
        g_h[n] = (float)v;
    }
}

__global__ void k_angles() {
    int a = blockIdx.x * blockDim.x + threadIdx.x;
    if (a < NA) {
        double ang = (2.0 * M_PI / (double)NA) * (double)a + M_PI / 2.0;
        double K = ((595.0 + 490.6) / 1.2858);   // DSD/DU (VOX cancels)
        float c = (float)cos(ang), s = (float)sin(ang);
        g_ang[a] = make_float4(c, s, (float)(K * cos(ang)), (float)(K * sin(ang)));
    }
}

// ---------------------------------------------------------------------------
// Per-row circular convolution + pair-table epilogue.
// 4 consecutive outputs per thread; 2-tap inner step uses vector LDS for both
// the row values and the newly-consumed filter taps (all even-aligned).
__global__ void __launch_bounds__(192) k_conv(const float* __restrict__ sino) {
    __shared__ float s_row[ND];
    __shared__ float s_e[ESZ];          // s_e[i] = h[(i - 736) mod 2048]
    __shared__ float s_out[ND + 1];
    int a = blockIdx.x;
    const float* row = sino + a * ND;
    for (int i = threadIdx.x; i < ND; i += blockDim.x)  s_row[i] = row[i];
    for (int i = threadIdx.x; i < ESZ; i += blockDim.x) s_e[i] = g_h[(i + 1312) & (PADN - 1)];
    if (threadIdx.x == 0) s_out[ND] = 0.0f;
    __syncthreads();

    int t = threadIdx.x;
    int j0 = 4 * t;                     // even => 8B-aligned vector LDS below
    if (j0 < ND) {
        const float*  e  = s_e + (j0 + 736);          // e[d] = h[(j0+d) mod 2048]
        const float2* e2 = (const float2*)s_e;
        const float2* r2 = (const float2*)s_row;

        float a0 = 0.f, a1 = 0.f, a2 = 0.f, a3 = 0.f;
        float h0 = e[0], h1 = e[1], h2 = e[2], h3 = e[3];
        #pragma unroll 4
        for (int m = 0; m < ND; m += 2) {
            float2 rr = r2[m >> 1];
            // tap m: taps h[j0-m .. j0-m+3] = h0..h3
            a0 = fmaf(rr.x, h0, a0);
            a1 = fmaf(rr.x, h1, a1);
            a2 = fmaf(rr.x, h2, a2);
            a3 = fmaf(rr.x, h3, a3);
            // fetch (h[j0-m-2], h[j0-m-1])  (even index => aligned)
            float2 hp = e2[(j0 + 734 - m) >> 1];
            // tap m+1: taps h[j0-m-1 .. j0-m+2] = (hp.y, h0, h1, h2)
            a0 = fmaf(rr.y, hp.y, a0);
            a1 = fmaf(rr.y, h0,  a1);
            a2 = fmaf(rr.y, h1,  a2);
            a3 = fmaf(rr.y, h2,  a3);
            // shift window down by 2
            h3 = h1; h2 = h0; h1 = hp.y; h0 = hp.x;
        }
        s_out[j0] = a0; s_out[j0 + 1] = a1; s_out[j0 + 2] = a2; s_out[j0 + 3] = a3;
    }
    __syncthreads();

    if (j0 < ND) {
        float2* dst = g_flt2 + a * ND;
        #pragma unroll
        for (int q = 0; q < 4; q++) {
            int i = j0 + q;
            dst[i] = make_float2(s_out[i], s_out[i + 1]);
        }
    }
}

// ---------------------------------------------------------------------------
// Pixel-driven fan-beam backprojection. 8 angles per iteration, one LDG.64
// per angle (pair table), weight = rcp^2 (D^2 and HU slope folded into h).
// frac from UNCLAMPED floor (round-5 semantics); only the index is clamped.
__global__ void __launch_bounds__(256) k_bp(float* __restrict__ out) {
    __shared__ float4 s_ang[NA];
    for (int t = threadIdx.y * blockDim.x + threadIdx.x; t < NA;
         t += blockDim.x * blockDim.y)
        s_ang[t] = g_ang[t];
    __syncthreads();

    int j = blockIdx.x * blockDim.x + threadIdx.x;  // x (fast dim)
    int i = blockIdx.y * blockDim.y + threadIdx.y;  // y (slow dim)
    float x = (float)j - 255.5f;
    float y = (float)i - 255.5f;

    const float Df = (float)((1.0 / 0.7) * 595.0);
    const float CD = 367.5f;                         // (ND-1)/2

    const float2* __restrict__ flt2 = g_flt2;
    float acc0 = 0.f, acc1 = 0.f, acc2 = 0.f, acc3 = 0.f;

    for (int a = 0; a < NA; a += 8) {
        int   off[8];
        float fr[8], wv[8];
        #pragma unroll
        for (int q = 0; q < 8; q++) {
            float4 tq = s_ang[a + q];
            float den = fmaf(-y, tq.y, fmaf(-x, tq.x, Df));
            float pe  = fmaf(y, tq.z, -x * tq.w);    // K*(y*cos - x*sin)
            float rcp;
            asm("rcp.approx.f32 %0, %1;" : "=f"(rcp) : "f"(den));
            float iu  = fmaf(pe, rcp, CD);
            int   i0  = __float2int_rd(iu);          // unclamped floor
            fr[q]  = iu - __int2float_rn(i0);        // true fraction
            int   ic  = min(max(i0, 0), ND - 2);     // clamp index only
            off[q] = (a + q) * ND + ic;
            wv[q] = ((unsigned)i0 <= (unsigned)(ND - 2)) ? rcp * rcp : 0.0f;
        }
        float2 v[8];
        #pragma unroll
        for (int q = 0; q < 8; q++) v[q] = __ldg(flt2 + off[q]);
        #pragma unroll
        for (int q = 0; q < 8; q += 4) {
            acc0 = fmaf(wv[q],     fmaf(fr[q],     v[q].y     - v[q].x,     v[q].x),     acc0);
            acc1 = fmaf(wv[q + 1], fmaf(fr[q + 1], v[q + 1].y - v[q + 1].x, v[q + 1].x), acc1);
            acc2 = fmaf(wv[q + 2], fmaf(fr[q + 2], v[q + 2].y - v[q + 2].x, v[q + 2].x), acc2);
            acc3 = fmaf(wv[q + 3], fmaf(fr[q + 3], v[q + 3].y - v[q + 3].x, v[q + 3].x), acc3);
        }
    }
    float acc = (acc0 + acc1) + (acc2 + acc3);

    const float B = (float)(24.0 / 4096.0);
    out[i * NP + j] = acc + B;
}

// ---------------------------------------------------------------------------
extern "C" void kernel_launch(void* const* d_in, const int* in_sizes, int n_in,
                              void* d_out, int out_size) {
    const float* x = (const float*)d_in[0];   // (1,1,1152,736) f32
    float* out = (float*)d_out;               // (1,1,512,512) f32

    k_filt_coeff<<<HALF, 128>>>();
    k_spatial<<<PADN, 128>>>();
    k_angles<<<(NA + 255) / 256, 256>>>();
    k_conv<<<NA, 192>>>(x);
    dim3 bb(32, 8), gb(NP / 32, NP / 8);
    k_bp<<<gb, bb>>>(out);
}